// round 3
// baseline (speedup 1.0000x reference)
#include <cuda_runtime.h>
#include <math.h>

#define NSTEP 100
#define B_TOTAL 2048
#define WARPS_PER_CTA 8
#define THREADS 256
#define NCTAS (B_TOTAL / WARPS_PER_CTA)

// Shared layout (floats):
//  w2s   : 13312  (w2 transposed to [c][ky][kx][oc], oc contiguous)
//          -- prologue-only xs (8*256) overlays the first 2048 floats of w2s
//  wfP4  : 1152   (288 float4: per (p,lane): wf row0/row1 for oc=2l and 2l+1)
//  dec   : 468 u32 (per layer-1 element: (w2 byte offset)<<9 | 9-bit validity)
//  w1s   : 208
//  b1s   : 16
//  cur1s : 8*480  (per-warp constant input current, zero-padded)
#define SMEM_FLOATS (13312 + 1152 + 468 + 208 + 16 + 8*480)

__global__ __launch_bounds__(THREADS, 3) void snn_kernel(
    const float* __restrict__ x,  const float* __restrict__ w1, const float* __restrict__ b1,
    const float* __restrict__ w2, const float* __restrict__ b2, const float* __restrict__ wf,
    const float* __restrict__ bf, float* __restrict__ out)
{
    extern __shared__ float smem[];
    float*    w2s  = smem;                                   // 13312
    float*    xs   = smem;                                   // prologue overlay (8*256)
    float4*   wfP4 = (float4*)(smem + 13312);                // 288 f4
    unsigned* dec  = (unsigned*)(smem + 13312 + 1152);       // 468
    float*    w1s  = (float*)(dec + 468);                    // 208
    float*    b1s  = w1s + 208;                              // 16
    float*    cur1s= b1s + 16;                               // 8*480

    const int tid  = threadIdx.x;
    const int wid  = tid >> 5;
    const int lane = tid & 31;
    const int b    = blockIdx.x * WARPS_PER_CTA + wid;

    // ---- prologue stage 1: small tables + input image (xs overlays w2s) ----
    for (int idx = tid; idx < 288; idx += THREADS) {         // wf permute: idx = p*32 + l
        int p = idx >> 5, l = idx & 31;
        int i0 = (2 * l) * 9 + p, i1 = (2 * l + 1) * 9 + p;
        wfP4[idx] = make_float4(wf[i0], wf[576 + i0], wf[i1], wf[576 + i1]);
    }
    for (int e = tid; e < 468; e += THREADS) {               // decode LUT for sparse conv2
        int c = e / 36, r = e - c * 36, iy = r / 6, ix = r - iy * 6;
        int s0 = iy * 4 + ix;
        unsigned vm = 0;
        for (int oy = 0; oy < 3; oy++)
            for (int ox = 0; ox < 3; ox++) {
                int ky = iy - oy, kx = ix - ox;
                if (ky >= 0 && ky < 4 && kx >= 0 && kx < 4) vm |= 1u << (oy * 3 + ox);
            }
        dec[e] = ((unsigned)(c * 4096 + s0 * 256) << 9) | vm;
    }
    if (tid < 208) w1s[tid] = w1[tid];
    if (tid < 13)  b1s[tid] = b1[tid];
    {
        float4* xs4 = (float4*)(xs + wid * 256);
        const float4* xg = (const float4*)(x + (size_t)b * 256);
        xs4[lane] = xg[lane];
        xs4[lane + 32] = xg[lane + 32];
    }
    __syncthreads();

    // ---- prologue stage 2: cur1 = maxpool2(conv1(x)+b1) ----
    {
        const float* xw = xs + wid * 256;
        float* cw = cur1s + wid * 480;
        #pragma unroll
        for (int k = 0; k < 15; k++) {
            int e = k * 32 + lane;
            float val = 0.f;
            if (e < 468) {
                int c = e / 36, r = e - c * 36, py = r / 6, px = r - py * 6;
                float m = -INFINITY;
                #pragma unroll
                for (int dy = 0; dy < 2; dy++)
                #pragma unroll
                for (int dx = 0; dx < 2; dx++) {
                    int iy0 = 2 * py + dy, ix0 = 2 * px + dx;
                    float s = 0.f;
                    #pragma unroll
                    for (int ky = 0; ky < 4; ky++)
                    #pragma unroll
                    for (int kx = 0; kx < 4; kx++)
                        s = fmaf(xw[(iy0 + ky) * 16 + ix0 + kx], w1s[c * 16 + ky * 4 + kx], s);
                    s = __fadd_rn(s, b1s[c]);
                    m = fmaxf(m, s);
                }
                val = m;
            }
            cw[k * 32 + lane] = val;   // zero-pad e in [468,480)
        }
    }
    __syncthreads();

    // ---- prologue stage 3: w2 transpose into smem (overwrites xs) ----
    for (int idx = tid; idx < 13312; idx += THREADS) {       // w2[oc][c*16+kk] -> w2s[(c*16+kk)*64+oc]
        int oc = idx / 208; int r = idx - oc * 208;
        w2s[r * 64 + oc] = w2[idx];
    }
    __syncthreads();

    // ---- recurrent state in registers ----
    float v1[15], i1[15];
    #pragma unroll
    for (int k = 0; k < 15; k++) { v1[k] = 0.f; i1[k] = 0.f; }
    float2 b2p = ((const float2*)b2)[lane];     // oc = 2*lane, 2*lane+1
    float2 v2[9], i2[9];
    #pragma unroll
    for (int p = 0; p < 9; p++) {
        v2[p] = make_float2(0.f, 0.f);
        i2[p] = make_float2(0.f, 0.f);
    }
    float v30 = 0.f, i30 = 0.f, v31 = 0.f, i31 = 0.f, s0 = 0.f, s1 = 0.f;
    const float bf0 = bf[0], bf1 = bf[1];
    const char* w2bytes = (const char*)w2s + lane * 8;
    const float* cw = cur1s + wid * 480;
    float2* outv = (float2*)(out + 2 * B_TOTAL) + b;

    // ---- 100 timesteps ----
    // Reordered step: layer2 LIF + FC + layer3 first (consume i2 holding cur2
    // contributions through t-1), then decay i2 (+b2) and let the layer-1
    // sparse loop accumulate spike weights directly into i2 for step t.
    for (int t = 0; t < NSTEP; t++) {
        // layer 2 LIF + FC (branch-free)
        float c30 = 0.f, c31 = 0.f;
        #pragma unroll
        for (int p = 0; p < 9; p++) {
            float vdx = __fadd_rn(v2[p].x, __fmul_rn(0.1f, __fsub_rn(i2[p].x, v2[p].x)));
            float vdy = __fadd_rn(v2[p].y, __fmul_rn(0.1f, __fsub_rn(i2[p].y, v2[p].y)));
            bool zx = vdx > 1.0f, zy = vdy > 1.0f;
            v2[p].x = zx ? 0.f : vdx;
            v2[p].y = zy ? 0.f : vdy;
            i2[p].x = __fadd_rn(__fmul_rn(0.8f, i2[p].x), b2p.x);
            i2[p].y = __fadd_rn(__fmul_rn(0.8f, i2[p].y), b2p.y);
            float4 q = wfP4[p * 32 + lane];
            c30 = __fadd_rn(c30, zx ? q.x : 0.0f);
            c31 = __fadd_rn(c31, zx ? q.y : 0.0f);
            c30 = __fadd_rn(c30, zy ? q.z : 0.0f);
            c31 = __fadd_rn(c31, zy ? q.w : 0.0f);
        }
        #pragma unroll
        for (int o = 16; o > 0; o >>= 1) {
            c30 += __shfl_xor_sync(0xffffffffu, c30, o);
            c31 += __shfl_xor_sync(0xffffffffu, c31, o);
        }
        float cur30 = __fadd_rn(c30, bf0);
        float cur31 = __fadd_rn(c31, bf1);

        // layer 3 LIF (redundant across lanes; lane 0 records)
        float vd0 = __fadd_rn(v30, __fmul_rn(0.1f, __fsub_rn(i30, v30)));
        float vd1 = __fadd_rn(v31, __fmul_rn(0.1f, __fsub_rn(i31, v31)));
        bool z0 = vd0 > 1.0f, z1 = vd1 > 1.0f;
        v30 = z0 ? 0.f : vd0;
        v31 = z1 ? 0.f : vd1;
        i30 = __fadd_rn(__fmul_rn(0.8f, i30), cur30);
        i31 = __fadd_rn(__fmul_rn(0.8f, i31), cur31);
        s0 += z0 ? 1.f : 0.f;
        s1 += z1 ? 1.f : 0.f;
        if (lane == 0) outv[t * B_TOTAL] = make_float2(v30, v31);

        if (t == NSTEP - 1) break;   // layer-1 work at the last step is dead

        // layer 1 LIF + sparse conv2 accumulation directly into i2
        #pragma unroll
        for (int k = 0; k < 15; k++) {
            float cur = cw[k * 32 + lane];
            float vd = __fadd_rn(v1[k], __fmul_rn(0.1f, __fsub_rn(i1[k], v1[k])));
            bool z = vd > 1.0f;
            v1[k] = z ? 0.f : vd;
            i1[k] = __fadd_rn(__fmul_rn(0.8f, i1[k]), cur);
            unsigned m = __ballot_sync(0xffffffffu, z);
            while (m) {
                int j = __ffs(m) - 1;
                m &= m - 1;
                unsigned d = dec[k * 32 + j];
                const char* base = w2bytes + (d >> 9);
                unsigned vm = d & 511u;
                #pragma unroll
                for (int p = 0; p < 9; p++) {
                    const int cpos = (p / 3) * 4 + (p % 3);
                    if (vm & (1u << p)) {
                        float2 wv = *(const float2*)(base - cpos * 256);
                        i2[p].x = __fadd_rn(i2[p].x, wv.x);
                        i2[p].y = __fadd_rn(i2[p].y, wv.y);
                    }
                }
            }
        }
    }
    if (lane == 0) ((float2*)out)[b] = make_float2(s0, s1);
}

extern "C" void kernel_launch(void* const* d_in, const int* in_sizes, int n_in,
                              void* d_out, int out_size) {
    const float* x  = (const float*)d_in[0];
    const float* w1 = (const float*)d_in[1];
    const float* b1 = (const float*)d_in[2];
    const float* w2 = (const float*)d_in[3];
    const float* b2 = (const float*)d_in[4];
    const float* wf = (const float*)d_in[5];
    const float* bf = (const float*)d_in[6];
    float* out = (float*)d_out;

    size_t shmem = (size_t)SMEM_FLOATS * sizeof(float);
    cudaFuncSetAttribute(snn_kernel, cudaFuncAttributeMaxDynamicSharedMemorySize, (int)shmem);
    snn_kernel<<<NCTAS, THREADS, shmem>>>(x, w1, b1, w2, b2, wf, bf, out);
}

// round 4
// speedup vs baseline: 1.4056x; 1.4056x over previous
#include <cuda_runtime.h>
#include <math.h>

#define NSTEP 100
#define B_TOTAL 2048
#define ELEMS_PER_CTA 8
#define THREADS 512
#define NCTAS (B_TOTAL / ELEMS_PER_CTA)   // 256

// Shared layout (floats):
//  w2s   : 13312  (w2 transposed to [c][ky][kx][oc], oc contiguous)
//          -- prologue-only overlay: xs (8*256) at [0,2048), w1s/b1s at [2048,2272)
//  wf2   : 1152   (576 float2: wf2[p*64+oc] = {wf[0][oc*9+p], wf[1][oc*9+p]})
//  dec   : 468 u32 (per layer-1 element: (w2 byte offset)<<9 | 9-bit validity)
//  cur1s : 8*480  (per-element constant input current, zero-padded)
//  syncA : 8*40 u32 (per elem: 2 bufs x 16 ballot slots, then 2 bufs x float2 partial)
#define SMEM_FLOATS (13312 + 1152 + 468 + 8*480 + 8*40)

__global__ __launch_bounds__(THREADS, 2) void snn_kernel(
    const float* __restrict__ x,  const float* __restrict__ w1, const float* __restrict__ b1,
    const float* __restrict__ w2, const float* __restrict__ b2, const float* __restrict__ wf,
    const float* __restrict__ bf, float* __restrict__ out)
{
    extern __shared__ float smem[];
    float*    w2s   = smem;                                   // 13312
    float2*   wf2   = (float2*)(smem + 13312);                // 576 f2
    unsigned* dec   = (unsigned*)(smem + 13312 + 1152);       // 468
    float*    cur1s = (float*)(dec + 468);                    // 8*480
    unsigned* syncA = (unsigned*)(cur1s + 8*480);             // 8*40
    // prologue-only overlays inside w2s:
    float*    xs    = smem;                                   // 8*256
    float*    w1s   = smem + 2048;                            // 208
    float*    b1s   = smem + 2048 + 208;                      // 13

    const int tid  = threadIdx.x;
    const int wid  = tid >> 5;
    const int lane = tid & 31;
    const int h    = wid & 1;           // half within the pair
    const int elem = wid >> 1;          // 0..7
    const int b    = blockIdx.x * ELEMS_PER_CTA + elem;
    const int oc   = h * 32 + lane;     // this lane's layer-2 output channel

    // ---- prologue stage 1: tables + input image (overlays w2s) ----
    for (int w = tid; w < 576; w += THREADS) {                // wf2[p*64+oc]
        int p = w >> 6, o = w & 63;
        wf2[w] = make_float2(wf[o * 9 + p], wf[576 + o * 9 + p]);
    }
    for (int e = tid; e < 468; e += THREADS) {                // decode LUT
        int c = e / 36, r = e - c * 36, iy = r / 6, ix = r - iy * 6;
        int s0 = iy * 4 + ix;
        unsigned vm = 0;
        for (int oy = 0; oy < 3; oy++)
            for (int ox = 0; ox < 3; ox++) {
                int ky = iy - oy, kx = ix - ox;
                if (ky >= 0 && ky < 4 && kx >= 0 && kx < 4) vm |= 1u << (oy * 3 + ox);
            }
        dec[e] = ((unsigned)(c * 4096 + s0 * 256) << 9) | vm;
    }
    if (tid < 208) w1s[tid] = w1[tid];
    if (tid < 13)  b1s[tid] = b1[tid];
    {   // each warp loads half of its element's image (64 float4 per elem)
        float4* xs4 = (float4*)(xs + elem * 256);
        const float4* xg = (const float4*)(x + (size_t)b * 256);
        xs4[h * 32 + lane] = xg[h * 32 + lane];
    }
    __syncthreads();

    // ---- prologue stage 2: cur1 = maxpool2(conv1(x)+b1), split by k ----
    {
        const float* xw = xs + elem * 256;
        float* cw = cur1s + elem * 480;
        #pragma unroll
        for (int kk = 0; kk < 8; kk++) {
            int k = h * 8 + kk;         // h0: 0..7, h1: 8..15 (15 skipped)
            if (k < 15) {
                int e = k * 32 + lane;
                float val = 0.f;
                if (e < 468) {
                    int c = e / 36, r = e - c * 36, py = r / 6, px = r - py * 6;
                    float m = -INFINITY;
                    #pragma unroll
                    for (int dy = 0; dy < 2; dy++)
                    #pragma unroll
                    for (int dx = 0; dx < 2; dx++) {
                        int iy0 = 2 * py + dy, ix0 = 2 * px + dx;
                        float s = 0.f;
                        #pragma unroll
                        for (int ky = 0; ky < 4; ky++)
                        #pragma unroll
                        for (int kx = 0; kx < 4; kx++)
                            s = fmaf(xw[(iy0 + ky) * 16 + ix0 + kx], w1s[c * 16 + ky * 4 + kx], s);
                        s = __fadd_rn(s, b1s[c]);
                        m = fmaxf(m, s);
                    }
                    val = m;
                }
                cw[k * 32 + lane] = val;   // zero-pad e in [468,480)
            }
        }
    }
    __syncthreads();

    // ---- prologue stage 3: w2 transpose into smem (overwrites overlays) ----
    for (int idx = tid; idx < 13312; idx += THREADS) {       // w2[oc][c*16+kk] -> w2s[(c*16+kk)*64+oc]
        int o = idx / 208; int r = idx - o * 208;
        w2s[r * 64 + o] = w2[idx];
    }
    __syncthreads();

    // ---- recurrent state in registers (per half) ----
    float v1[8], i1[8];
    #pragma unroll
    for (int kk = 0; kk < 8; kk++) { v1[kk] = 0.f; i1[kk] = 0.f; }
    float v2[9], i2[9];
    #pragma unroll
    for (int p = 0; p < 9; p++) { v2[p] = 0.f; i2[p] = 0.f; }
    const float b2v = b2[oc];
    float v30 = 0.f, i30 = 0.f, v31 = 0.f, i31 = 0.f, s0 = 0.f, s1 = 0.f;   // h0 only

    unsigned* ball = syncA + elem * 40;           // [buf*16 + k], k=0..14
    float2*   part = (float2*)(ball + 32);        // [buf], written by h1 only
    const char* w2base = (const char*)w2s + oc * 4;
    const float* cw = cur1s + elem * 480;
    float2* outv = (float2*)(out + 2 * B_TOTAL) + b;
    const int barid = elem + 1;                   // named barrier per pair

    // ---- 100 timesteps ----
    for (int t = 0; t < NSTEP; t++) {
        const int buf = t & 1;

        // layer 2 LIF (own 32 oc) + FC partial
        float c0 = 0.f, c1 = 0.f;
        #pragma unroll
        for (int p = 0; p < 9; p++) {
            float vd = __fadd_rn(v2[p], __fmul_rn(0.1f, __fsub_rn(i2[p], v2[p])));
            bool z = vd > 1.0f;
            v2[p] = z ? 0.f : vd;
            i2[p] = __fadd_rn(__fmul_rn(0.8f, i2[p]), b2v);
            float2 q = wf2[p * 64 + oc];
            c0 = __fadd_rn(c0, z ? q.x : 0.0f);
            c1 = __fadd_rn(c1, z ? q.y : 0.0f);
        }
        #pragma unroll
        for (int o = 16; o > 0; o >>= 1) {
            c0 += __shfl_xor_sync(0xffffffffu, c0, o);
            c1 += __shfl_xor_sync(0xffffffffu, c1, o);
        }
        if (h == 1 && lane == 0) part[buf] = make_float2(c0, c1);

        // layer 1 LIF (own k's) -> ballots to smem
        if (t < NSTEP - 1) {
            #pragma unroll
            for (int kk = 0; kk < 8; kk++) {
                int k = h * 8 + kk;
                if (k < 15) {
                    float cur = cw[k * 32 + lane];
                    float vd = __fadd_rn(v1[kk], __fmul_rn(0.1f, __fsub_rn(i1[kk], v1[kk])));
                    bool z = vd > 1.0f;
                    v1[kk] = z ? 0.f : vd;
                    i1[kk] = __fadd_rn(__fmul_rn(0.8f, i1[kk]), cur);
                    unsigned m = __ballot_sync(0xffffffffu, z);
                    if (lane == 0) ball[buf * 16 + k] = m;
                }
            }
        }

        // pair sync: ballots + FC partial visible
        asm volatile("bar.sync %0, 64;" :: "r"(barid));

        // layer 3 (h0 only; reads partner's FC partial)
        if (h == 0) {
            float2 pp = part[buf];
            float cur30 = __fadd_rn(__fadd_rn(c0, pp.x), bf[0]);
            float cur31 = __fadd_rn(__fadd_rn(c1, pp.y), bf[1]);
            float vd0 = __fadd_rn(v30, __fmul_rn(0.1f, __fsub_rn(i30, v30)));
            float vd1 = __fadd_rn(v31, __fmul_rn(0.1f, __fsub_rn(i31, v31)));
            bool z0 = vd0 > 1.0f, z1 = vd1 > 1.0f;
            v30 = z0 ? 0.f : vd0;
            v31 = z1 ? 0.f : vd1;
            i30 = __fadd_rn(__fmul_rn(0.8f, i30), cur30);
            i31 = __fadd_rn(__fmul_rn(0.8f, i31), cur31);
            s0 += z0 ? 1.f : 0.f;
            s1 += z1 ? 1.f : 0.f;
            if (lane == 0) outv[t * B_TOTAL] = make_float2(v30, v31);
        }

        // sparse conv2 accumulation into own i2 (all 15 ballots, k ascending)
        if (t < NSTEP - 1) {
            #pragma unroll
            for (int k = 0; k < 15; k++) {
                unsigned m = ball[buf * 16 + k];
                while (m) {
                    int j = __ffs(m) - 1;
                    m &= m - 1;
                    unsigned d = dec[k * 32 + j];
                    const char* base = w2base + (d >> 9);
                    unsigned vm = d & 511u;
                    #pragma unroll
                    for (int p = 0; p < 9; p++) {
                        const int cpos = (p / 3) * 4 + (p % 3);
                        if (vm & (1u << p)) {
                            float wv = *(const float*)(base - cpos * 256);
                            i2[p] = __fadd_rn(i2[p], wv);
                        }
                    }
                }
            }
        }
    }
    if (h == 0 && lane == 0) ((float2*)out)[b] = make_float2(s0, s1);
}

extern "C" void kernel_launch(void* const* d_in, const int* in_sizes, int n_in,
                              void* d_out, int out_size) {
    const float* x  = (const float*)d_in[0];
    const float* w1 = (const float*)d_in[1];
    const float* b1 = (const float*)d_in[2];
    const float* w2 = (const float*)d_in[3];
    const float* b2 = (const float*)d_in[4];
    const float* wf = (const float*)d_in[5];
    const float* bf = (const float*)d_in[6];
    float* out = (float*)d_out;

    size_t shmem = (size_t)SMEM_FLOATS * sizeof(float);
    cudaFuncSetAttribute(snn_kernel, cudaFuncAttributeMaxDynamicSharedMemorySize, (int)shmem);
    snn_kernel<<<NCTAS, THREADS, shmem>>>(x, w1, b1, w2, b2, wf, bf, out);
}

// round 5
// speedup vs baseline: 1.7940x; 1.2763x over previous
#include <cuda_runtime.h>
#include <math.h>

#define NSTEP 100
#define B_TOTAL 2048
#define ELEMS_PER_CTA 8
#define THREADS 512
#define NCTAS (B_TOTAL / ELEMS_PER_CTA)   // 256

// Shared layout (float offsets):
//  w2s  [0, 13312)        w2 transposed: [c][ky][kx][oc], oc contiguous
//        prologue overlay: xs 8*256 at [0,2048), w1s at [2048,2256), b1s at [2256,2269)
//  dsum [13312, 21952)    per-k dense sums: dsum[k*576 + p*64 + oc]
//  wf2  [21952, 23104)    576 float2: wf2[p*64+oc] = {wf[0][oc*9+p], wf[1][oc*9+p]}
//  dec  [23104, 23572)    468 u32: (w2 byte offset)<<9 | 9-bit validity mask
//  xch  [23572, 28180)    8 elems * 576: per-elem [contributor_half][p][32 oc slots]
//  part [28180, 28196)    8 elems * float2 FC partial (h1 -> h0)
#define OFF_DSUM 13312
#define OFF_WF2  21952
#define OFF_DEC  23104
#define OFF_XCH  23572
#define OFF_PART 28180
#define SMEM_FLOATS 28196   // 112,784 bytes; 2 CTAs fit in 228KB

__global__ __launch_bounds__(THREADS, 2) void snn_kernel(
    const float* __restrict__ x,  const float* __restrict__ w1, const float* __restrict__ b1,
    const float* __restrict__ w2, const float* __restrict__ b2, const float* __restrict__ wf,
    const float* __restrict__ bf, float* __restrict__ out)
{
    extern __shared__ float smem[];
    float2*   wf2v  = (float2*)(smem + OFF_WF2);
    unsigned* decs  = (unsigned*)(smem + OFF_DEC);
    const float2* dsumF2 = (const float2*)(smem + OFF_DSUM);
    // prologue overlays (inside w2s region):
    float* xs  = smem;            // 8*256
    float* w1s = smem + 2048;     // 208
    float* b1s = smem + 2256;     // 13

    const int tid  = threadIdx.x;
    const int wid  = tid >> 5;
    const int lane = tid & 31;
    const int h    = wid & 1;           // half: h0 -> k 0..7, h1 -> k 8..14
    const int elem = wid >> 1;          // 0..7
    const int b    = blockIdx.x * ELEMS_PER_CTA + elem;
    const int oc   = h * 32 + lane;     // this lane's layer-2 oc for LIF/FC

    // ---- prologue stage 1: small tables + input image ----
    for (int w = tid; w < 576; w += THREADS) {
        int p = w >> 6, o = w & 63;
        wf2v[w] = make_float2(wf[o * 9 + p], wf[576 + o * 9 + p]);
    }
    for (int e = tid; e < 468; e += THREADS) {
        int c = e / 36, r = e - c * 36, iy = r / 6, ix = r - iy * 6;
        int s0i = iy * 4 + ix;
        unsigned vm = 0;
        for (int oy = 0; oy < 3; oy++)
            for (int ox = 0; ox < 3; ox++) {
                int ky = iy - oy, kx = ix - ox;
                if (ky >= 0 && ky < 4 && kx >= 0 && kx < 4) vm |= 1u << (oy * 3 + ox);
            }
        decs[e] = ((unsigned)(c * 4096 + s0i * 256) << 9) | vm;
    }
    if (tid < 208) w1s[tid] = w1[tid];
    if (tid < 13)  b1s[tid] = b1[tid];
    {   // each warp loads half of its element's image
        float4* xs4 = (float4*)(xs + elem * 256);
        const float4* xg = (const float4*)(x + (size_t)b * 256);
        xs4[h * 32 + lane] = xg[h * 32 + lane];
    }
    __syncthreads();

    // ---- prologue stage 2: cur1 = maxpool2(conv1(x)+b1) -> registers ----
    float cur[8], v1[8];
    {
        const float* xw = xs + elem * 256;
        #pragma unroll
        for (int kk = 0; kk < 8; kk++) {
            cur[kk] = 0.f; v1[kk] = 0.f;
            if (kk < 8 - h) {
                int k = h * 8 + kk;
                int e = k * 32 + lane;
                if (e < 468) {
                    int c = e / 36, r = e - c * 36, py = r / 6, px = r - py * 6;
                    float m = -INFINITY;
                    #pragma unroll
                    for (int dy = 0; dy < 2; dy++)
                    #pragma unroll
                    for (int dx = 0; dx < 2; dx++) {
                        int iy0 = 2 * py + dy, ix0 = 2 * px + dx;
                        float s = 0.f;
                        #pragma unroll
                        for (int ky = 0; ky < 4; ky++)
                        #pragma unroll
                        for (int kx = 0; kx < 4; kx++)
                            s = fmaf(xw[(iy0 + ky) * 16 + ix0 + kx], w1s[c * 16 + ky * 4 + kx], s);
                        s = __fadd_rn(s, b1s[c]);
                        m = fmaxf(m, s);
                    }
                    cur[kk] = m;
                }
            }
        }
    }
    __syncthreads();

    // ---- prologue stage 3: w2 transpose (overwrites overlays) ----
    for (int idx = tid; idx < 13312; idx += THREADS) {   // w2[oc][c*16+kk] -> w2s[(c*16+kk)*64+oc]
        int o = idx / 208; int r = idx - o * 208;
        smem[r * 64 + o] = w2[idx];
    }
    __syncthreads();

    // ---- prologue stage 4: per-k dense weight sums ----
    for (int idx = tid; idx < 8640; idx += THREADS) {
        int k = idx / 576; int r = idx - k * 576; int p = r >> 6; int o = r & 63;
        int cpos = (p / 3) * 4 + (p % 3);
        int cnt = (k == 14) ? 20 : 32;
        float s = 0.f;
        for (int j = 0; j < cnt; j++) {
            unsigned d = decs[k * 32 + j];
            if ((d >> p) & 1u)
                s = __fadd_rn(s, smem[(d >> 11) - cpos * 64 + o]);
        }
        smem[OFF_DSUM + idx] = s;
    }
    __syncthreads();

    // ---- recurrent state ----
    float2 b2p = ((const float2*)b2)[lane];   // oc pair (2*lane, 2*lane+1) for sacc
    float v2[9], i2[9];
    #pragma unroll
    for (int p = 0; p < 9; p++) { v2[p] = 0.f; i2[p] = 0.f; }
    float v30 = 0.f, i30 = 0.f, v31 = 0.f, i31 = 0.f, so0 = 0.f, so1 = 0.f;   // h0 only
    const float bf0 = bf[0], bf1 = bf[1];
    const float b2own = b2[oc];   (void)b2own;
    float ft = 0.f;   // i1(t) = cur * ft;  ft' = 0.8 ft + 1 (i1 has no reset)

    float* xchE = smem + OFF_XCH + elem * 576;
    float2* partE = (float2*)(smem + OFF_PART) + elem;
    float2* outv = (float2*)(out + 2 * B_TOTAL) + b;
    const int barid = elem + 1;

    // ---- 100 timesteps ----
    for (int t = 0; t < NSTEP; t++) {
        // ===== phase A: layer-1 LIF (own k half) + accumulate sacc (full 64 oc, pair/lane)
        float sx[9], sy[9];
        #pragma unroll
        for (int p = 0; p < 9; p++) {
            sx[p] = (h == 0) ? b2p.x : 0.f;
            sy[p] = (h == 0) ? b2p.y : 0.f;
        }
        #pragma unroll
        for (int kk = 0; kk < 8; kk++) {
            if (kk < 8 - h) {
                const int k = h * 8 + kk;
                float i1v = __fmul_rn(cur[kk], ft);
                float vd = __fadd_rn(v1[kk], __fmul_rn(0.1f, __fsub_rn(i1v, v1[kk])));
                bool z = vd > 1.0f;
                v1[kk] = z ? 0.f : vd;
                unsigned m = __ballot_sync(0xffffffffu, z);
                const int cnt = (k == 14) ? 20 : 32;
                const unsigned kmask = (k == 14) ? 0xFFFFFu : 0xFFFFFFFFu;
                int n = __popc(m);
                if (2 * n > cnt + 1) {
                    // complement: add dense sum, subtract non-spiking rows
                    const float2* dp = dsumF2 + k * 288 + lane;
                    #pragma unroll
                    for (int p = 0; p < 9; p++) {
                        float2 dv = dp[p * 32];
                        sx[p] = __fadd_rn(sx[p], dv.x);
                        sy[p] = __fadd_rn(sy[p], dv.y);
                    }
                    unsigned use = ~m & kmask;
                    while (use) {
                        int j = __ffs(use) - 1; use &= use - 1;
                        unsigned d = decs[(k << 5) + j];
                        const float2* base = (const float2*)smem + (d >> 12) + lane;
                        unsigned vmm = d & 511u;
                        #pragma unroll
                        for (int p = 0; p < 9; p++) {
                            const int cpos = (p / 3) * 4 + (p % 3);
                            if (vmm & (1u << p)) {
                                float2 w = base[-cpos * 32];
                                sx[p] = __fsub_rn(sx[p], w.x);
                                sy[p] = __fsub_rn(sy[p], w.y);
                            }
                        }
                    }
                } else {
                    unsigned use = m;
                    while (use) {
                        int j = __ffs(use) - 1; use &= use - 1;
                        unsigned d = decs[(k << 5) + j];
                        const float2* base = (const float2*)smem + (d >> 12) + lane;
                        unsigned vmm = d & 511u;
                        #pragma unroll
                        for (int p = 0; p < 9; p++) {
                            const int cpos = (p / 3) * 4 + (p % 3);
                            if (vmm & (1u << p)) {
                                float2 w = base[-cpos * 32];
                                sx[p] = __fadd_rn(sx[p], w.x);
                                sy[p] = __fadd_rn(sy[p], w.y);
                            }
                        }
                    }
                }
            }
        }
        ft = __fadd_rn(__fmul_rn(0.8f, ft), 1.0f);

        // write partner-oc share of own sacc to smem (16 active lanes)
        if ((lane >> 4) == (1 - h)) {
            int s = (lane & 15) << 1;
            float* dst = xchE + h * 288 + s;
            #pragma unroll
            for (int p = 0; p < 9; p++)
                *(float2*)(dst + p * 32) = make_float2(sx[p], sy[p]);
        }
        asm volatile("bar.sync %0, 64;" :: "r"(barid));   // bar A

        // ===== phase B: merge sacc for own oc; layer-2 LIF + FC (oc-split)
        float c0 = 0.f, c1 = 0.f;
        const int src = (h << 4) + (lane >> 1);
        const float* prtB = xchE + (1 - h) * 288 + lane;
        #pragma unroll
        for (int p = 0; p < 9; p++) {
            float a  = __shfl_sync(0xffffffffu, sx[p], src);
            float bb = __shfl_sync(0xffffffffu, sy[p], src);
            float own = (lane & 1) ? bb : a;
            float tot = __fadd_rn(own, prtB[p * 32]);   // (b2 + sum_h0) + sum_h1
            float vd = __fadd_rn(v2[p], __fmul_rn(0.1f, __fsub_rn(i2[p], v2[p])));
            bool z2 = vd > 1.0f;
            v2[p] = z2 ? 0.f : vd;
            i2[p] = __fadd_rn(__fmul_rn(0.8f, i2[p]), tot);
            float2 q = wf2v[p * 64 + oc];
            c0 = __fadd_rn(c0, z2 ? q.x : 0.0f);
            c1 = __fadd_rn(c1, z2 ? q.y : 0.0f);
        }
        #pragma unroll
        for (int o = 16; o > 0; o >>= 1) {
            c0 += __shfl_xor_sync(0xffffffffu, c0, o);
            c1 += __shfl_xor_sync(0xffffffffu, c1, o);
        }
        if (h == 1 && lane == 0) *partE = make_float2(c0, c1);
        asm volatile("bar.sync %0, 64;" :: "r"(barid));   // bar B

        // ===== layer 3 (h0 only)
        if (h == 0) {
            float2 pp = *partE;
            float cur30 = __fadd_rn(__fadd_rn(c0, pp.x), bf0);
            float cur31 = __fadd_rn(__fadd_rn(c1, pp.y), bf1);
            float vd0 = __fadd_rn(v30, __fmul_rn(0.1f, __fsub_rn(i30, v30)));
            float vd1 = __fadd_rn(v31, __fmul_rn(0.1f, __fsub_rn(i31, v31)));
            bool z0 = vd0 > 1.0f, z1 = vd1 > 1.0f;
            v30 = z0 ? 0.f : vd0;
            v31 = z1 ? 0.f : vd1;
            i30 = __fadd_rn(__fmul_rn(0.8f, i30), cur30);
            i31 = __fadd_rn(__fmul_rn(0.8f, i31), cur31);
            so0 += z0 ? 1.f : 0.f;
            so1 += z1 ? 1.f : 0.f;
            if (lane == 0) outv[t * B_TOTAL] = make_float2(v30, v31);
        }
    }
    if (h == 0 && lane == 0) ((float2*)out)[b] = make_float2(so0, so1);
}

extern "C" void kernel_launch(void* const* d_in, const int* in_sizes, int n_in,
                              void* d_out, int out_size) {
    const float* x  = (const float*)d_in[0];
    const float* w1 = (const float*)d_in[1];
    const float* b1 = (const float*)d_in[2];
    const float* w2 = (const float*)d_in[3];
    const float* b2 = (const float*)d_in[4];
    const float* wf = (const float*)d_in[5];
    const float* bf = (const float*)d_in[6];
    float* out = (float*)d_out;

    size_t shmem = (size_t)SMEM_FLOATS * sizeof(float);
    cudaFuncSetAttribute(snn_kernel, cudaFuncAttributeMaxDynamicSharedMemorySize, (int)shmem);
    snn_kernel<<<NCTAS, THREADS, shmem>>>(x, w1, b1, w2, b2, wf, bf, out);
}